// round 3
// baseline (speedup 1.0000x reference)
#include <cuda_runtime.h>
#include <cstdint>
#include <cstddef>

#define KDIM 4096
#define NDIM 4096
#define BDIM 8192
#define NG   32

// Scratch: rotated, norm-folded, tf32-rounded weights (row-major N x K). 64 MB.
__device__ float g_Wr[(size_t)NDIM * KDIM];

static __device__ __forceinline__ uint32_t cvt_tf32(float x) {
    uint32_t r;
    asm("cvt.rna.tf32.f32 %0, %1;" : "=r"(r) : "f"(x));
    return r;
}

// ---------------------------------------------------------------------------
// Kernel 1: dequant + rotate + scale weights.
// Wr[n, g*128+k] = (norms[n,g]/sqrt(128)) * sum_j Pi_g[j,k] * cb[idx[n, g*128+j]]
// Block: (g, 64 n-rows). 256 threads = 128 k-cols x 2 row-halves, 4 rows/thread.
// ---------------------------------------------------------------------------
__global__ void rotate_weights(const int* __restrict__ indices,
                               const float* __restrict__ codebook,
                               const float* __restrict__ norms,
                               const float* __restrict__ rot) {
    extern __shared__ float sm[];
    float* Pi = sm;              // 128*128 floats (64 KB)
    float* Wl = sm + 128 * 128;  // 8*128 floats
    __shared__ float cb[16];
    const int g = blockIdx.x;
    const int nblk = blockIdx.y * 64;
    const int tid = threadIdx.x;
    if (tid < 16) cb[tid] = codebook[tid];
    const float4* Pig = (const float4*)(rot + (size_t)g * 128 * 128);
    float4* Pi4 = (float4*)Pi;
#pragma unroll
    for (int i = 0; i < 16; ++i) Pi4[tid + 256 * i] = Pig[tid + 256 * i];
    __syncthreads();
    const int kcol = tid & 127;
    const int rh = tid >> 7;
    const float RS = 0.088388347648318447f;  // 1/sqrt(128)

    for (int c = 0; c < 8; ++c) {
        const int n0 = nblk + c * 8;
        {   // dequant 8 rows x 128, norms folded in
            const int flat = tid * 4;
            const int r = flat >> 7;
            const int j = flat & 127;
            const int4 iv = *(const int4*)(indices + (size_t)(n0 + r) * KDIM + g * 128 + j);
            const float nm = norms[(n0 + r) * NG + g] * RS;
            Wl[flat + 0] = cb[iv.x] * nm;
            Wl[flat + 1] = cb[iv.y] * nm;
            Wl[flat + 2] = cb[iv.z] * nm;
            Wl[flat + 3] = cb[iv.w] * nm;
        }
        __syncthreads();
        float a0 = 0.f, a1 = 0.f, a2 = 0.f, a3 = 0.f;
        const float* w0 = Wl + (rh * 4 + 0) * 128;
        const float* w1 = Wl + (rh * 4 + 1) * 128;
        const float* w2 = Wl + (rh * 4 + 2) * 128;
        const float* w3 = Wl + (rh * 4 + 3) * 128;
#pragma unroll
        for (int j4 = 0; j4 < 32; ++j4) {
            const float p0 = Pi[(j4 * 4 + 0) * 128 + kcol];
            const float p1 = Pi[(j4 * 4 + 1) * 128 + kcol];
            const float p2 = Pi[(j4 * 4 + 2) * 128 + kcol];
            const float p3 = Pi[(j4 * 4 + 3) * 128 + kcol];
            float4 v;
            v = *(const float4*)(w0 + j4 * 4); a0 += p0 * v.x + p1 * v.y + p2 * v.z + p3 * v.w;
            v = *(const float4*)(w1 + j4 * 4); a1 += p0 * v.x + p1 * v.y + p2 * v.z + p3 * v.w;
            v = *(const float4*)(w2 + j4 * 4); a2 += p0 * v.x + p1 * v.y + p2 * v.z + p3 * v.w;
            v = *(const float4*)(w3 + j4 * 4); a3 += p0 * v.x + p1 * v.y + p2 * v.z + p3 * v.w;
        }
        __syncthreads();
        uint32_t* dst = (uint32_t*)g_Wr;
        const size_t base = (size_t)(n0 + rh * 4) * KDIM + g * 128 + kcol;
        dst[base + 0 * (size_t)KDIM] = cvt_tf32(a0);
        dst[base + 1 * (size_t)KDIM] = cvt_tf32(a1);
        dst[base + 2 * (size_t)KDIM] = cvt_tf32(a2);
        dst[base + 3 * (size_t)KDIM] = cvt_tf32(a3);
    }
}

// ---------------------------------------------------------------------------
// Kernel 2: out(8192x4096) = X(8192x4096) @ Wr^T, tf32 mma, fp32 accumulate.
// BM=BN=128, BK=32, 3-stage cp.async pipeline, 8 warps (2x4), warp tile 64x32.
// Smem row stride 36 floats -> fragment loads conflict-free (bank = lane).
// ---------------------------------------------------------------------------
#define BM 128
#define BN 128
#define BK 32
#define STAGES 3
#define SSTR 36
#define STAGE_F (BM * SSTR)

static __device__ __forceinline__ void cp16(uint32_t dst, const void* src) {
    asm volatile("cp.async.cg.shared.global [%0], [%1], 16;\n" :: "r"(dst), "l"(src));
}

static __device__ __forceinline__ void mma_tf32(float* d, const uint32_t* a, const uint32_t* b) {
    asm volatile(
        "mma.sync.aligned.m16n8k8.row.col.f32.tf32.tf32.f32 "
        "{%0,%1,%2,%3}, {%4,%5,%6,%7}, {%8,%9}, {%0,%1,%2,%3};\n"
        : "+f"(d[0]), "+f"(d[1]), "+f"(d[2]), "+f"(d[3])
        : "r"(a[0]), "r"(a[1]), "r"(a[2]), "r"(a[3]), "r"(b[0]), "r"(b[1]));
}

__global__ __launch_bounds__(256) void gemm_tf32(const float* __restrict__ X,
                                                 float* __restrict__ out) {
    extern __shared__ float sm[];
    float* As = sm;
    float* Bs = sm + STAGES * STAGE_F;
    const int tid = threadIdx.x;
    const int warp = tid >> 5, lane = tid & 31;
    const int wm = (warp >> 2) * 64, wn = (warp & 3) * 32;
    const int bm = blockIdx.y * BM, bn = blockIdx.x * BN;
    const float* Wr = g_Wr;

    float acc[4][4][4];
#pragma unroll
    for (int i = 0; i < 4; ++i)
#pragma unroll
        for (int j = 0; j < 4; ++j)
#pragma unroll
            for (int r = 0; r < 4; ++r) acc[i][j][r] = 0.f;

    const int cm = tid >> 3;          // copy row base (+32*i)
    const int ck = (tid & 7) * 4;     // copy col (float4)
    const uint32_t sAu = (uint32_t)__cvta_generic_to_shared(As);
    const uint32_t sBu = (uint32_t)__cvta_generic_to_shared(Bs);

    // Prologue: fill STAGES-1 stages
#pragma unroll
    for (int s = 0; s < STAGES - 1; ++s) {
        const int k0 = s * BK;
#pragma unroll
        for (int i = 0; i < 4; ++i) {
            const int m = cm + 32 * i;
            cp16(sAu + (uint32_t)((s * STAGE_F + m * SSTR + ck) << 2),
                 X + (size_t)(bm + m) * KDIM + k0 + ck);
            cp16(sBu + (uint32_t)((s * STAGE_F + m * SSTR + ck) << 2),
                 Wr + (size_t)(bn + m) * KDIM + k0 + ck);
        }
        asm volatile("cp.async.commit_group;\n");
    }
    asm volatile("cp.async.wait_group %0;\n" :: "n"(STAGES - 2));
    __syncthreads();

    const int KT = KDIM / BK;  // 128
#pragma unroll 1
    for (int kt = 0; kt < KT; ++kt) {
        // Prefetch tile kt+STAGES-1 (always commit a group, possibly empty,
        // so wait_group<STAGES-2> semantics stay exact at the loop tail)
        if (kt + STAGES - 1 < KT) {
            const int s = (kt + STAGES - 1) % STAGES;
            const int k0 = (kt + STAGES - 1) * BK;
#pragma unroll
            for (int i = 0; i < 4; ++i) {
                const int m = cm + 32 * i;
                cp16(sAu + (uint32_t)((s * STAGE_F + m * SSTR + ck) << 2),
                     X + (size_t)(bm + m) * KDIM + k0 + ck);
                cp16(sBu + (uint32_t)((s * STAGE_F + m * SSTR + ck) << 2),
                     Wr + (size_t)(bn + m) * KDIM + k0 + ck);
            }
        }
        asm volatile("cp.async.commit_group;\n");

        const int sr = kt % STAGES;
        const float* At = As + sr * STAGE_F + wm * SSTR;
        const float* Bt = Bs + sr * STAGE_F + wn * SSTR;
#pragma unroll
        for (int ks = 0; ks < 4; ++ks) {
            const int kb = ks * 8;
            uint32_t af[4][4], bf[4][2];
#pragma unroll
            for (int mt = 0; mt < 4; ++mt) {
                const float* p = At + (mt * 16 + (lane >> 2)) * SSTR + kb + (lane & 3);
                af[mt][0] = cvt_tf32(p[0]);            // (row,      c)
                af[mt][1] = cvt_tf32(p[8 * SSTR]);     // (row+8,    c)
                af[mt][2] = cvt_tf32(p[4]);            // (row,      c+4)
                af[mt][3] = cvt_tf32(p[8 * SSTR + 4]); // (row+8,    c+4)
            }
#pragma unroll
            for (int nt = 0; nt < 4; ++nt) {
                const float* p = Bt + (nt * 8 + (lane >> 2)) * SSTR + kb + (lane & 3);
                bf[nt][0] = __float_as_uint(p[0]);     // Wr pre-rounded to tf32
                bf[nt][1] = __float_as_uint(p[4]);
            }
#pragma unroll
            for (int mt = 0; mt < 4; ++mt)
#pragma unroll
                for (int nt = 0; nt < 4; ++nt)
                    mma_tf32(acc[mt][nt], af[mt], bf[nt]);
        }
        asm volatile("cp.async.wait_group %0;\n" :: "n"(STAGES - 2));
        __syncthreads();
    }

    // Epilogue: fp32 out, coalesced float2 stores
#pragma unroll
    for (int mt = 0; mt < 4; ++mt) {
#pragma unroll
        for (int nt = 0; nt < 4; ++nt) {
            const int row = bm + wm + mt * 16 + (lane >> 2);
            const int col = bn + wn + nt * 8 + (lane & 3) * 2;
            float2 v0 = make_float2(acc[mt][nt][0], acc[mt][nt][1]);
            float2 v1 = make_float2(acc[mt][nt][2], acc[mt][nt][3]);
            *(float2*)(out + (size_t)row * NDIM + col) = v0;
            *(float2*)(out + (size_t)(row + 8) * NDIM + col) = v1;
        }
    }
}

// ---------------------------------------------------------------------------
extern "C" void kernel_launch(void* const* d_in, const int* in_sizes, int n_in,
                              void* d_out, int out_size) {
    const float* x        = (const float*)d_in[0];   // (8192, 4096) f32
    const int*   indices  = (const int*)d_in[1];     // (4096, 4096) i32
    const float* codebook = (const float*)d_in[2];   // (16,) f32
    const float* norms    = (const float*)d_in[3];   // (4096, 32) f32
    const float* rot      = (const float*)d_in[4];   // (32, 128, 128) f32
    float* out = (float*)d_out;                      // (8192, 4096) f32

    const int rot_smem  = (128 * 128 + 8 * 128) * 4;           // 69632 B
    const int gemm_smem = STAGES * STAGE_F * 2 * 4;            // 110592 B
    cudaFuncSetAttribute(rotate_weights, cudaFuncAttributeMaxDynamicSharedMemorySize, rot_smem);
    cudaFuncSetAttribute(gemm_tf32, cudaFuncAttributeMaxDynamicSharedMemorySize, gemm_smem);

    rotate_weights<<<dim3(NG, NDIM / 64), 256, rot_smem>>>(indices, codebook, norms, rot);
    gemm_tf32<<<dim3(NDIM / BN, BDIM / BM), 256, gemm_smem>>>(x, out);
}